// round 14
// baseline (speedup 1.0000x reference)
#include <cuda_runtime.h>
#include <cuda_fp16.h>
#include <math.h>
#include <stdint.h>

#define BATCH 16
#define C 512
#define HW 1024
#define NGROUP 32
#define CPG 16
#define GSIZE (CPG*HW)
#define QK_SCALE 0.04419417382415922f  // 1/sqrt(512)

// -------- scratch (static device globals; no runtime allocation) --------
__device__ __half g_xt[BATCH*HW*C];     // normalized input, transposed [b][n][c]
__device__ __half g_qkv[BATCH*HW*3*C];  // [b][n][0..C)=Q, [C..2C)=K, [2C..3C)=V_t
__device__ __half g_s[BATCH*HW*HW];     // unnormalized probs exp(S*scale)
__device__ __half g_a[BATCH*HW*C];      // A_t [b][n][c]
__device__ __half g_hwqkv[3*C*C];       // Wq | Wk | Wv  (row-major [o][c])
__device__ __half g_hwo[C*C];
__device__ float  g_bqkv[3*C];          // bq | bk | bv
__device__ float  g_rsum[BATCH*HW];     // softmax row sums (atomic accumulated)

// ============================ fused prep ============================
__global__ __launch_bounds__(256) void prep_kernel(
    const float* __restrict__ inp,
    const float* __restrict__ gamma, const float* __restrict__ beta,
    const float* __restrict__ Wq, const float* __restrict__ Wk,
    const float* __restrict__ Wv, const float* __restrict__ Wo,
    const float* __restrict__ bq, const float* __restrict__ bk,
    const float* __restrict__ bv)
{
    if (blockIdx.x >= 1536) {
        int i = (blockIdx.x - 1536)*1024 + threadIdx.x*4;
        float4 z = {0.f, 0.f, 0.f, 0.f};
        *(float4*)(g_rsum + i) = z;
        return;
    }
    if (blockIdx.x >= 512) {
        int i = blockIdx.x - 512;
        int which = i >> 8;
        int blk = i & 255;
        const float* s = which == 0 ? Wq : which == 1 ? Wk : which == 2 ? Wv : Wo;
        __half* d = which == 3 ? g_hwo : (g_hwqkv + (size_t)which * C * C);
        int e = (blk*256 + threadIdx.x)*4;
        float4 v = *(const float4*)(s + e);
        *(__half2*)(d + e)     = __floats2half2_rn(v.x, v.y);
        *(__half2*)(d + e + 2) = __floats2half2_rn(v.z, v.w);
        if (i == 0) {
            int t = threadIdx.x;
            #pragma unroll
            for (int p = 0; p < 2; p++) {
                int j = t + p*256;
                g_bqkv[j] = bq[j];
                g_bqkv[C + j] = bk[j];
                g_bqkv[2*C + j] = bv[j];
            }
        }
        return;
    }

    int bg = blockIdx.x;
    int b = bg / NGROUP, g = bg % NGROUP;
    const float* src = inp + (size_t)bg * GSIZE;

    float vreg[4][CPG];
    float s = 0.f, ss = 0.f;
    #pragma unroll
    for (int p = 0; p < 4; p++) {
        int n = threadIdx.x + p*256;
        #pragma unroll
        for (int c = 0; c < CPG; c++) {
            float x = src[c*HW + n];
            vreg[p][c] = x;
            s += x; ss += x*x;
        }
    }
    __shared__ float sh1[8], sh2[8];
    #pragma unroll
    for (int o = 16; o > 0; o >>= 1) {
        s  += __shfl_down_sync(0xffffffffu, s,  o);
        ss += __shfl_down_sync(0xffffffffu, ss, o);
    }
    int lane = threadIdx.x & 31, wid = threadIdx.x >> 5;
    if (lane == 0) { sh1[wid] = s; sh2[wid] = ss; }
    __syncthreads();
    if (threadIdx.x == 0) {
        float t1 = 0.f, t2 = 0.f;
        #pragma unroll
        for (int i = 0; i < 8; i++) { t1 += sh1[i]; t2 += sh2[i]; }
        sh1[0] = t1; sh2[0] = t2;
    }
    __syncthreads();
    float mu   = sh1[0] * (1.f/GSIZE);
    float var  = sh2[0] * (1.f/GSIZE) - mu*mu;
    float rstd = rsqrtf(var + 1e-6f);

    float ga[CPG], be[CPG];
    #pragma unroll
    for (int c = 0; c < CPG; c++) {
        ga[c] = gamma[g*CPG + c] * rstd;
        be[c] = beta[g*CPG + c];
    }

    __half* dst = g_xt + (size_t)b*HW*C + g*CPG;
    #pragma unroll
    for (int p = 0; p < 4; p++) {
        int n = threadIdx.x + p*256;
        __half2 hh[8];
        #pragma unroll
        for (int c = 0; c < 8; c++) {
            float o0 = (vreg[p][2*c  ] - mu) * ga[2*c  ] + be[2*c  ];
            float o1 = (vreg[p][2*c+1] - mu) * ga[2*c+1] + be[2*c+1];
            hh[c] = __floats2half2_rn(o0, o1);
        }
        __half* d = dst + (size_t)n * C;
        *(uint4*)(d)     = *(uint4*)(hh);
        *(uint4*)(d + 8) = *(uint4*)(hh + 4);
    }
}

// ============================ unified TN fp16 GEMM (128x256x64) ============================
// C[b][m][n] = sum_k A[m][k]*B[n][k].  8 warps (2M x 4N), warp tile 64x64.
// BTRANS: B stored [k][n] n-contig. EXPSUM/RDIV: fused softmax epilogues.

#define BM 128
#define BN 256
#define A_BYTES 16384
#define B_BYTES 32768
#define STAGE_BYTES (A_BYTES + B_BYTES)   // 48 KB
#define NSTAGE 3
#define SMEM_TOT (NSTAGE*STAGE_BYTES)     // 144 KB
#define NTHR 256
#define BK 64

__device__ __forceinline__ void cp16(uint32_t saddr, const void* g) {
    asm volatile("cp.async.cg.shared.global [%0], [%1], 16;" :: "r"(saddr), "l"(g));
}
#define LDSM4(R0,R1,R2,R3,ADDR) \
    asm volatile("ldmatrix.sync.aligned.m8n8.x4.shared.b16 {%0,%1,%2,%3}, [%4];" \
        : "=r"(R0), "=r"(R1), "=r"(R2), "=r"(R3) : "r"(ADDR))
#define LDSM4T(R0,R1,R2,R3,ADDR) \
    asm volatile("ldmatrix.sync.aligned.m8n8.x4.trans.shared.b16 {%0,%1,%2,%3}, [%4];" \
        : "=r"(R0), "=r"(R1), "=r"(R2), "=r"(R3) : "r"(ADDR))

template<bool BROW, bool RES, bool OUTF, bool BTRANS, bool EXPSUM, bool RDIV>
__global__ __launch_bounds__(NTHR, 1) void gemm_tn(
    const __half* __restrict__ Ag, const __half* __restrict__ Bg,
    void* __restrict__ Cg, const float* __restrict__ bias,
    const float* __restrict__ resg, float* __restrict__ rs,
    int N, int K, int lda, int ldb, int ldc,
    long sA, long sB, long sC)
{
    extern __shared__ float smem[];
    const uint32_t smem_u32 = (uint32_t)__cvta_generic_to_shared(smem);

    const int t = threadIdx.x, lane = t & 31, w = t >> 5;
    const int m0 = blockIdx.y * BM, n0 = blockIdx.x * BN, b = blockIdx.z;
    const __half* Ab = Ag + (size_t)b * sA + (size_t)m0 * lda;
    const __half* Bb;
    if (BTRANS) Bb = Bg + (size_t)b * sB + n0;
    else        Bb = Bg + (size_t)b * sB + (size_t)n0 * ldb;

    // ---- staging offsets: A 4 units/thread, B 8 units/thread ----
    uint32_t sAoff[4], gAo[4];
    #pragma unroll
    for (int p = 0; p < 4; p++) {
        int idx = t + NTHR*p;
        int row = idx >> 3, gc = idx & 7;         // 128 rows x 8 units
        sAoff[p] = (uint32_t)((row*8 + (gc ^ (row & 7))) * 16);
        gAo[p] = (uint32_t)(row * lda + gc*8);
    }
    uint32_t sBoff[8], gBo[8];
    #pragma unroll
    for (int p = 0; p < 8; p++) {
        int idx = t + NTHR*p;
        if (BTRANS) {
            int row = idx >> 5, gc = idx & 31;    // 64 rows (k) x 32 units (256 n)
            sBoff[p] = (uint32_t)((row*32 + (gc ^ (row & 7))) * 16);
            gBo[p] = (uint32_t)(row * ldb + gc*8);
        } else {
            int row = idx >> 3, gc = idx & 7;     // 256 rows (n) x 8 units (64 k)
            sBoff[p] = (uint32_t)((row*8 + (gc ^ (row & 7))) * 16);
            gBo[p] = (uint32_t)(row * ldb + gc*8);
        }
    }

    // ---- fragment smem address precompute ----
    const int wm = (w & 1) * 64, wn = (w >> 1) * 64;
    int amrow[4], am7[4];
    #pragma unroll
    for (int mi = 0; mi < 4; mi++) {
        int m = wm + mi*16 + (lane & 7) + ((lane & 8) ? 8 : 0);
        amrow[mi] = m * 8; am7[mi] = m & 7;
    }
    const int kgA = (lane & 16) ? 1 : 0;

    int bnrow[4], bn7[4];
    uint32_t btoff[4];
    const int kgB = (lane & 8) ? 1 : 0;
    #pragma unroll
    for (int P = 0; P < 4; P++) {
        if (BTRANS) {
            int rk = (lane & 7) + ((lane & 8) ? 8 : 0);
            int ngU = ((wn + P*16) >> 3) + ((lane & 16) ? 1 : 0);
            btoff[P] = (uint32_t)((rk*32 + (ngU ^ (rk & 7))) * 16);
        } else {
            int n = wn + P*16 + (lane & 7) + ((lane & 16) ? 8 : 0);
            bnrow[P] = n * 8; bn7[P] = n & 7;
        }
    }

    float acc[4][8][4];
    #pragma unroll
    for (int i = 0; i < 4; i++)
        #pragma unroll
        for (int j = 0; j < 8; j++)
            #pragma unroll
            for (int r = 0; r < 4; r++) acc[i][j][r] = 0.f;

    const int NTILES = K >> 6;

    #pragma unroll
    for (int kt = 0; kt < 2; kt++) {
        uint32_t sa = smem_u32 + kt*STAGE_BYTES, sb = sa + A_BYTES;
        #pragma unroll
        for (int p = 0; p < 4; p++) cp16(sa + sAoff[p], Ab + gAo[p] + kt*BK);
        #pragma unroll
        for (int p = 0; p < 8; p++)
            cp16(sb + sBoff[p], Bb + gBo[p] + (BTRANS ? kt*BK*ldb : kt*BK));
        asm volatile("cp.async.commit_group;" ::: "memory");
    }

    int buf = 0, sbuf = 2;
    for (int kt = 0; kt < NTILES; kt++) {
        if (kt + 1 < NTILES) asm volatile("cp.async.wait_group 1;" ::: "memory");
        else                 asm volatile("cp.async.wait_group 0;" ::: "memory");
        __syncthreads();

        if (kt + 2 < NTILES) {
            int k0 = (kt + 2) << 6;
            uint32_t sa = smem_u32 + sbuf*STAGE_BYTES, sb = sa + A_BYTES;
            #pragma unroll
            for (int p = 0; p < 4; p++) cp16(sa + sAoff[p], Ab + gAo[p] + k0);
            #pragma unroll
            for (int p = 0; p < 8; p++)
                cp16(sb + sBoff[p], Bb + gBo[p] + (BTRANS ? k0*ldb : k0));
            asm volatile("cp.async.commit_group;" ::: "memory");
        }

        const uint32_t sa = smem_u32 + buf*STAGE_BYTES;
        const uint32_t sb = sa + A_BYTES;

        #pragma unroll
        for (int ks = 0; ks < 4; ks++) {
            unsigned a[4][4];
            #pragma unroll
            for (int mi = 0; mi < 4; mi++) {
                uint32_t ad = sa + (uint32_t)((amrow[mi] + ((2*ks + kgA) ^ am7[mi])) * 16);
                LDSM4(a[mi][0], a[mi][1], a[mi][2], a[mi][3], ad);
            }
            unsigned bf[8][2];
            #pragma unroll
            for (int P = 0; P < 4; P++) {
                if (BTRANS) {
                    uint32_t bd = sb + btoff[P] + (uint32_t)(ks * 8192);
                    LDSM4T(bf[2*P][0], bf[2*P][1], bf[2*P+1][0], bf[2*P+1][1], bd);
                } else {
                    uint32_t bd = sb + (uint32_t)((bnrow[P] + ((2*ks + kgB) ^ bn7[P])) * 16);
                    LDSM4(bf[2*P][0], bf[2*P][1], bf[2*P+1][0], bf[2*P+1][1], bd);
                }
            }
            #pragma unroll
            for (int mi = 0; mi < 4; mi++)
                #pragma unroll
                for (int ni = 0; ni < 8; ni++)
                    asm volatile(
                        "mma.sync.aligned.m16n8k16.row.col.f32.f16.f16.f32 "
                        "{%0,%1,%2,%3}, {%4,%5,%6,%7}, {%8,%9}, {%0,%1,%2,%3};"
                        : "+f"(acc[mi][ni][0]), "+f"(acc[mi][ni][1]),
                          "+f"(acc[mi][ni][2]), "+f"(acc[mi][ni][3])
                        : "r"(a[mi][0]), "r"(a[mi][1]), "r"(a[mi][2]), "r"(a[mi][3]),
                          "r"(bf[ni][0]), "r"(bf[ni][1]));
        }

        buf = (buf == 2) ? 0 : buf + 1;
        sbuf = (sbuf == 2) ? 0 : sbuf + 1;
    }

    // ---- epilogue ----
    float* rsb = (EXPSUM || RDIV) ? (rs + (size_t)b * HW) : nullptr;
    #pragma unroll
    for (int mi = 0; mi < 4; mi++) {
        int r0 = m0 + wm + mi*16 + (lane >> 2);
        float br0 = 0.f, br1 = 0.f;
        if (BROW) { br0 = bias[r0]; br1 = bias[r0 + 8]; }
        if (RDIV) { br0 = 1.f / rsb[r0]; br1 = 1.f / rsb[r0 + 8]; }
        float rsum0 = 0.f, rsum1 = 0.f;
        #pragma unroll
        for (int ni = 0; ni < 8; ni++) {
            int cc = n0 + wn + ni*8 + (lane & 3)*2;
            float v0 = acc[mi][ni][0], v1 = acc[mi][ni][1];
            float v2 = acc[mi][ni][2], v3 = acc[mi][ni][3];
            if (EXPSUM) {
                v0 = __expf(v0 * QK_SCALE); v1 = __expf(v1 * QK_SCALE);
                v2 = __expf(v2 * QK_SCALE); v3 = __expf(v3 * QK_SCALE);
                rsum0 += v0 + v1; rsum1 += v2 + v3;
            }
            if (BROW) { v0 += br0; v1 += br0; v2 += br1; v3 += br1; }
            if (RDIV) { v0 *= br0; v1 *= br0; v2 *= br1; v3 *= br1; }
            if (RES) {
                float2 ra = *(const float2*)(resg + (size_t)b*sC + (size_t)r0*ldc + cc);
                float2 rb = *(const float2*)(resg + (size_t)b*sC + (size_t)(r0+8)*ldc + cc);
                v0 += ra.x; v1 += ra.y; v2 += rb.x; v3 += rb.y;
            }
            if (OUTF) {
                float* Cb = (float*)Cg + (size_t)b * sC;
                float2 o0 = {v0, v1}, o1 = {v2, v3};
                *(float2*)(Cb + (size_t)r0*ldc + cc) = o0;
                *(float2*)(Cb + (size_t)(r0+8)*ldc + cc) = o1;
            } else {
                __half* Cb = (__half*)Cg + (size_t)b * sC;
                *(__half2*)(Cb + (size_t)r0*ldc + cc) = __floats2half2_rn(v0, v1);
                *(__half2*)(Cb + (size_t)(r0+8)*ldc + cc) = __floats2half2_rn(v2, v3);
            }
        }
        if (EXPSUM) {
            #pragma unroll
            for (int o = 1; o < 4; o <<= 1) {
                rsum0 += __shfl_xor_sync(0xffffffffu, rsum0, o);
                rsum1 += __shfl_xor_sync(0xffffffffu, rsum1, o);
            }
            if ((lane & 3) == 0) {
                atomicAdd(rsb + r0, rsum0);
                atomicAdd(rsb + r0 + 8, rsum1);
            }
        }
    }
}

// ============================ launch ============================
extern "C" void kernel_launch(void* const* d_in, const int* in_sizes, int n_in,
                              void* d_out, int out_size) {
    const float* inp   = (const float*)d_in[0];
    const float* gamma = (const float*)d_in[1];
    const float* beta  = (const float*)d_in[2];
    const float* Wq    = (const float*)d_in[3];
    const float* bq    = (const float*)d_in[4];
    const float* Wk    = (const float*)d_in[5];
    const float* bk    = (const float*)d_in[6];
    const float* Wv    = (const float*)d_in[7];
    const float* bv    = (const float*)d_in[8];
    const float* Wo    = (const float*)d_in[9];
    const float* bo    = (const float*)d_in[10];
    float* out = (float*)d_out;

    void *pxt, *pqkv, *ps, *pa, *hwqkv, *hwo, *pbqkv, *prs;
    cudaGetSymbolAddress(&pxt, g_xt);
    cudaGetSymbolAddress(&pqkv, g_qkv);
    cudaGetSymbolAddress(&ps, g_s);
    cudaGetSymbolAddress(&pa, g_a);
    cudaGetSymbolAddress(&hwqkv, g_hwqkv);
    cudaGetSymbolAddress(&hwo, g_hwo);
    cudaGetSymbolAddress(&pbqkv, g_bqkv);
    cudaGetSymbolAddress(&prs, g_rsum);

    const long sNC  = (long)HW * C;
    const long sN3C = (long)HW * 3 * C;
    const long sHH  = (long)HW * HW;

    cudaFuncSetAttribute(gemm_tn<true,false,false,false,false,false>, cudaFuncAttributeMaxDynamicSharedMemorySize, SMEM_TOT);
    cudaFuncSetAttribute(gemm_tn<false,false,false,false,true,false>, cudaFuncAttributeMaxDynamicSharedMemorySize, SMEM_TOT);
    cudaFuncSetAttribute(gemm_tn<false,false,false,true,false,true>, cudaFuncAttributeMaxDynamicSharedMemorySize, SMEM_TOT);
    cudaFuncSetAttribute(gemm_tn<true,true,true,false,false,false>, cudaFuncAttributeMaxDynamicSharedMemorySize, SMEM_TOT);

    // GroupNorm (512) + weight convert (1024) + rsum zero (16)
    prep_kernel<<<1552, 256>>>(inp, gamma, beta, Wq, Wk, Wv, Wo, bq, bk, bv);

    // QKV_t[n][o] = sum_c x_t[n][c] Wqkv[o][c] + bqkv[o]  (M=1024, N=1536)
    gemm_tn<true,false,false,false,false,false><<<dim3(3*C/BN, HW/BM, BATCH), NTHR, SMEM_TOT>>>(
        (const __half*)pxt, (const __half*)hwqkv, pqkv, (const float*)pbqkv, nullptr, nullptr,
        3*C, C, C, C, 3*C, sNC, 0, sN3C);

    // P_unnorm[n][m] = exp(scale * sum_c Q K) ; rsum[n] += row sums
    gemm_tn<false,false,false,false,true,false><<<dim3(HW/BN, HW/BM, BATCH), NTHR, SMEM_TOT>>>(
        (const __half*)pqkv, (const __half*)pqkv + C, ps, nullptr, nullptr, (float*)prs,
        HW, C, 3*C, 3*C, HW, sN3C, sN3C, sHH);

    // A_t[n][c] = (sum_m P_unnorm[n][m] V_t[m][c]) / rsum[n]
    gemm_tn<false,false,false,true,false,true><<<dim3(C/BN, HW/BM, BATCH), NTHR, SMEM_TOT>>>(
        (const __half*)ps, (const __half*)pqkv + 2*C, pa, nullptr, nullptr, (float*)prs,
        C, HW, HW, 3*C, C, sHH, sN3C, sNC);

    // out[o][n] = sum_c Wo[o][c] A_t[n][c] + bo[o] + inp[o][n]   (fp32 out)
    gemm_tn<true,true,true,false,false,false><<<dim3(HW/BN, C/BM, BATCH), NTHR, SMEM_TOT>>>(
        (const __half*)hwo, (const __half*)pa, out, bo, inp, nullptr,
        HW, C, C, C, HW, 0, sNC, sNC);
}

// round 15
// speedup vs baseline: 1.1524x; 1.1524x over previous
#include <cuda_runtime.h>
#include <cuda_fp16.h>
#include <math.h>
#include <stdint.h>

#define BATCH 16
#define C 512
#define HW 1024
#define NGROUP 32
#define CPG 16
#define GSIZE (CPG*HW)
#define QK_SCALE 0.04419417382415922f  // 1/sqrt(512)

// -------- scratch (static device globals; no runtime allocation) --------
__device__ __half g_xt[BATCH*HW*C];     // normalized input, transposed [b][n][c]
__device__ __half g_qkv[BATCH*HW*3*C];  // [b][n][0..C)=Q, [C..2C)=K, [2C..3C)=V_t
__device__ __half g_s[BATCH*HW*HW];     // unnormalized probs exp(S*scale)
__device__ __half g_a[BATCH*HW*C];      // A_t [b][n][c]
__device__ __half g_hwqkv[3*C*C];       // Wq | Wk | Wv  (row-major [o][c])
__device__ __half g_hwo[C*C];
__device__ float  g_bqkv[3*C];          // bq | bk | bv
__device__ float  g_rsum[BATCH*HW];     // softmax row sums (atomic accumulated)

// ============================ fused prep ============================
__global__ __launch_bounds__(256) void prep_kernel(
    const float* __restrict__ inp,
    const float* __restrict__ gamma, const float* __restrict__ beta,
    const float* __restrict__ Wq, const float* __restrict__ Wk,
    const float* __restrict__ Wv, const float* __restrict__ Wo,
    const float* __restrict__ bq, const float* __restrict__ bk,
    const float* __restrict__ bv)
{
    if (blockIdx.x >= 1536) {
        int i = (blockIdx.x - 1536)*1024 + threadIdx.x*4;
        float4 z = {0.f, 0.f, 0.f, 0.f};
        *(float4*)(g_rsum + i) = z;
        return;
    }
    if (blockIdx.x >= 512) {
        int i = blockIdx.x - 512;
        int which = i >> 8;
        int blk = i & 255;
        const float* s = which == 0 ? Wq : which == 1 ? Wk : which == 2 ? Wv : Wo;
        __half* d = which == 3 ? g_hwo : (g_hwqkv + (size_t)which * C * C);
        int e = (blk*256 + threadIdx.x)*4;
        float4 v = *(const float4*)(s + e);
        *(__half2*)(d + e)     = __floats2half2_rn(v.x, v.y);
        *(__half2*)(d + e + 2) = __floats2half2_rn(v.z, v.w);
        if (i == 0) {
            int t = threadIdx.x;
            #pragma unroll
            for (int p = 0; p < 2; p++) {
                int j = t + p*256;
                g_bqkv[j] = bq[j];
                g_bqkv[C + j] = bk[j];
                g_bqkv[2*C + j] = bv[j];
            }
        }
        return;
    }

    int bg = blockIdx.x;
    int b = bg / NGROUP, g = bg % NGROUP;
    const float* src = inp + (size_t)bg * GSIZE;

    float vreg[4][CPG];
    float s = 0.f, ss = 0.f;
    #pragma unroll
    for (int p = 0; p < 4; p++) {
        int n = threadIdx.x + p*256;
        #pragma unroll
        for (int c = 0; c < CPG; c++) {
            float x = src[c*HW + n];
            vreg[p][c] = x;
            s += x; ss += x*x;
        }
    }
    __shared__ float sh1[8], sh2[8];
    #pragma unroll
    for (int o = 16; o > 0; o >>= 1) {
        s  += __shfl_down_sync(0xffffffffu, s,  o);
        ss += __shfl_down_sync(0xffffffffu, ss, o);
    }
    int lane = threadIdx.x & 31, wid = threadIdx.x >> 5;
    if (lane == 0) { sh1[wid] = s; sh2[wid] = ss; }
    __syncthreads();
    if (threadIdx.x == 0) {
        float t1 = 0.f, t2 = 0.f;
        #pragma unroll
        for (int i = 0; i < 8; i++) { t1 += sh1[i]; t2 += sh2[i]; }
        sh1[0] = t1; sh2[0] = t2;
    }
    __syncthreads();
    float mu   = sh1[0] * (1.f/GSIZE);
    float var  = sh2[0] * (1.f/GSIZE) - mu*mu;
    float rstd = rsqrtf(var + 1e-6f);

    float ga[CPG], be[CPG];
    #pragma unroll
    for (int c = 0; c < CPG; c++) {
        ga[c] = gamma[g*CPG + c] * rstd;
        be[c] = beta[g*CPG + c];
    }

    __half* dst = g_xt + (size_t)b*HW*C + g*CPG;
    #pragma unroll
    for (int p = 0; p < 4; p++) {
        int n = threadIdx.x + p*256;
        __half2 hh[8];
        #pragma unroll
        for (int c = 0; c < 8; c++) {
            float o0 = (vreg[p][2*c  ] - mu) * ga[2*c  ] + be[2*c  ];
            float o1 = (vreg[p][2*c+1] - mu) * ga[2*c+1] + be[2*c+1];
            hh[c] = __floats2half2_rn(o0, o1);
        }
        __half* d = dst + (size_t)n * C;
        *(uint4*)(d)     = *(uint4*)(hh);
        *(uint4*)(d + 8) = *(uint4*)(hh + 4);
    }
}

// ============================ unified TN fp16 GEMM (128x128x64, 4 warps) ============================
// C[b][m][n] = sum_k A[m][k]*B[n][k].  A always [m][k] k-contig.
// BTRANS: B stored [k][n] n-contig (ldmatrix.trans).
// EXPSUM: epilogue writes exp(acc*QK_SCALE), atomically accumulates row sums.
// RDIV:   epilogue scales rows by 1/rsum (loads hoisted, MLP=8).

#define STAGE_BYTES 32768
#define NSTAGE 3
#define SMEM_TOT (NSTAGE*STAGE_BYTES)
#define NTHR 128
#define BK 64

__device__ __forceinline__ void cp16(uint32_t saddr, const void* g) {
    asm volatile("cp.async.cg.shared.global [%0], [%1], 16;" :: "r"(saddr), "l"(g));
}
#define LDSM4(R0,R1,R2,R3,ADDR) \
    asm volatile("ldmatrix.sync.aligned.m8n8.x4.shared.b16 {%0,%1,%2,%3}, [%4];" \
        : "=r"(R0), "=r"(R1), "=r"(R2), "=r"(R3) : "r"(ADDR))
#define LDSM4T(R0,R1,R2,R3,ADDR) \
    asm volatile("ldmatrix.sync.aligned.m8n8.x4.trans.shared.b16 {%0,%1,%2,%3}, [%4];" \
        : "=r"(R0), "=r"(R1), "=r"(R2), "=r"(R3) : "r"(ADDR))

template<bool BROW, bool RES, bool OUTF, bool BTRANS, bool EXPSUM, bool RDIV>
__global__ __launch_bounds__(NTHR, 2) void gemm_tn(
    const __half* __restrict__ Ag, const __half* __restrict__ Bg,
    void* __restrict__ Cg, const float* __restrict__ bias,
    const float* __restrict__ resg, float* __restrict__ rs,
    int N, int K, int lda, int ldb, int ldc,
    long sA, long sB, long sC)
{
    extern __shared__ float smem[];
    const uint32_t smem_u32 = (uint32_t)__cvta_generic_to_shared(smem);

    const int t = threadIdx.x, lane = t & 31, w = t >> 5;
    const int m0 = blockIdx.y * 128, n0 = blockIdx.x * 128, b = blockIdx.z;
    const __half* Ab = Ag + (size_t)b * sA + (size_t)m0 * lda;
    const __half* Bb;
    if (BTRANS) Bb = Bg + (size_t)b * sB + n0;
    else        Bb = Bg + (size_t)b * sB + (size_t)n0 * ldb;

    uint32_t sAoff[8], gAo[8], sBoff[8], gBo[8];
    #pragma unroll
    for (int p = 0; p < 8; p++) {
        int idx = t + NTHR*p;
        int rowA = idx >> 3, gcA = idx & 7;
        sAoff[p] = (uint32_t)((rowA*8 + (gcA ^ (rowA & 7))) * 16);
        gAo[p] = (uint32_t)(rowA * lda + gcA*8);
        if (BTRANS) {
            int row = idx >> 4, gc = idx & 15;
            sBoff[p] = (uint32_t)((row*16 + (gc ^ (row & 7))) * 16);
            gBo[p] = (uint32_t)(row * ldb + gc*8);
        } else {
            sBoff[p] = sAoff[p];
            gBo[p] = (uint32_t)(rowA * ldb + gcA*8);
        }
    }

    const int wm = (w & 1) * 64, wn = (w >> 1) * 64;
    int amrow[4], am7[4];
    #pragma unroll
    for (int mi = 0; mi < 4; mi++) {
        int m = wm + mi*16 + (lane & 7) + ((lane & 8) ? 8 : 0);
        amrow[mi] = m * 8; am7[mi] = m & 7;
    }
    const int kgA = (lane & 16) ? 1 : 0;

    int bnrow[4], bn7[4];
    uint32_t btoff[4];
    const int kgB = (lane & 8) ? 1 : 0;
    #pragma unroll
    for (int P = 0; P < 4; P++) {
        if (BTRANS) {
            int rk = (lane & 7) + ((lane & 8) ? 8 : 0);
            int ngU = ((wn + P*16) >> 3) + ((lane & 16) ? 1 : 0);
            btoff[P] = (uint32_t)((rk*16 + (ngU ^ (rk & 7))) * 16);
        } else {
            int n = wn + P*16 + (lane & 7) + ((lane & 16) ? 8 : 0);
            bnrow[P] = n * 8; bn7[P] = n & 7;
        }
    }

    float acc[4][8][4];
    #pragma unroll
    for (int i = 0; i < 4; i++)
        #pragma unroll
        for (int j = 0; j < 8; j++)
            #pragma unroll
            for (int r = 0; r < 4; r++) acc[i][j][r] = 0.f;

    const int NTILES = K >> 6;

    #pragma unroll
    for (int kt = 0; kt < 2; kt++) {
        uint32_t sa = smem_u32 + kt*STAGE_BYTES, sb = sa + 16384;
        #pragma unroll
        for (int p = 0; p < 8; p++) cp16(sa + sAoff[p], Ab + gAo[p] + kt*BK);
        #pragma unroll
        for (int p = 0; p < 8; p++)
            cp16(sb + sBoff[p], Bb + gBo[p] + (BTRANS ? kt*BK*ldb : kt*BK));
        asm volatile("cp.async.commit_group;" ::: "memory");
    }

    int buf = 0, sbuf = 2;
    for (int kt = 0; kt < NTILES; kt++) {
        if (kt + 1 < NTILES) asm volatile("cp.async.wait_group 1;" ::: "memory");
        else                 asm volatile("cp.async.wait_group 0;" ::: "memory");
        __syncthreads();

        if (kt + 2 < NTILES) {
            int k0 = (kt + 2) << 6;
            uint32_t sa = smem_u32 + sbuf*STAGE_BYTES, sb = sa + 16384;
            #pragma unroll
            for (int p = 0; p < 8; p++) cp16(sa + sAoff[p], Ab + gAo[p] + k0);
            #pragma unroll
            for (int p = 0; p < 8; p++)
                cp16(sb + sBoff[p], Bb + gBo[p] + (BTRANS ? k0*ldb : k0));
            asm volatile("cp.async.commit_group;" ::: "memory");
        }

        const uint32_t sa = smem_u32 + buf*STAGE_BYTES;
        const uint32_t sb = sa + 16384;

        #pragma unroll
        for (int ks = 0; ks < 4; ks++) {
            unsigned a[4][4];
            #pragma unroll
            for (int mi = 0; mi < 4; mi++) {
                uint32_t ad = sa + (uint32_t)((amrow[mi] + ((2*ks + kgA) ^ am7[mi])) * 16);
                LDSM4(a[mi][0], a[mi][1], a[mi][2], a[mi][3], ad);
            }
            unsigned bf[8][2];
            #pragma unroll
            for (int P = 0; P < 4; P++) {
                if (BTRANS) {
                    uint32_t bd = sb + btoff[P] + (uint32_t)(ks * 4096);
                    LDSM4T(bf[2*P][0], bf[2*P][1], bf[2*P+1][0], bf[2*P+1][1], bd);
                } else {
                    uint32_t bd = sb + (uint32_t)((bnrow[P] + ((2*ks + kgB) ^ bn7[P])) * 16);
                    LDSM4(bf[2*P][0], bf[2*P][1], bf[2*P+1][0], bf[2*P+1][1], bd);
                }
            }
            #pragma unroll
            for (int mi = 0; mi < 4; mi++)
                #pragma unroll
                for (int ni = 0; ni < 8; ni++)
                    asm volatile(
                        "mma.sync.aligned.m16n8k16.row.col.f32.f16.f16.f32 "
                        "{%0,%1,%2,%3}, {%4,%5,%6,%7}, {%8,%9}, {%0,%1,%2,%3};"
                        : "+f"(acc[mi][ni][0]), "+f"(acc[mi][ni][1]),
                          "+f"(acc[mi][ni][2]), "+f"(acc[mi][ni][3])
                        : "r"(a[mi][0]), "r"(a[mi][1]), "r"(a[mi][2]), "r"(a[mi][3]),
                          "r"(bf[ni][0]), "r"(bf[ni][1]));
        }

        buf = (buf == 2) ? 0 : buf + 1;
        sbuf = (sbuf == 2) ? 0 : sbuf + 1;
    }

    // ---- epilogue (hoisted row-scalar loads: MLP=8 instead of serial) ----
    float* rsb = (EXPSUM || RDIV) ? (rs + (size_t)b * HW) : nullptr;
    float rowA8[8];   // per-mi pair of row scalars (bias or 1/rsum)
    #pragma unroll
    for (int mi = 0; mi < 4; mi++) {
        int r0 = m0 + wm + mi*16 + (lane >> 2);
        if (BROW) { rowA8[2*mi] = bias[r0]; rowA8[2*mi+1] = bias[r0 + 8]; }
        else if (RDIV) { rowA8[2*mi] = rsb[r0]; rowA8[2*mi+1] = rsb[r0 + 8]; }
        else { rowA8[2*mi] = 0.f; rowA8[2*mi+1] = 0.f; }
    }
    if (RDIV) {
        #pragma unroll
        for (int i = 0; i < 8; i++) rowA8[i] = 1.f / rowA8[i];
    }

    #pragma unroll
    for (int mi = 0; mi < 4; mi++) {
        int r0 = m0 + wm + mi*16 + (lane >> 2);
        float br0 = rowA8[2*mi], br1 = rowA8[2*mi+1];
        float rsum0 = 0.f, rsum1 = 0.f;
        #pragma unroll
        for (int ni = 0; ni < 8; ni++) {
            int cc = n0 + wn + ni*8 + (lane & 3)*2;
            float v0 = acc[mi][ni][0], v1 = acc[mi][ni][1];
            float v2 = acc[mi][ni][2], v3 = acc[mi][ni][3];
            if (EXPSUM) {
                v0 = __expf(v0 * QK_SCALE); v1 = __expf(v1 * QK_SCALE);
                v2 = __expf(v2 * QK_SCALE); v3 = __expf(v3 * QK_SCALE);
                rsum0 += v0 + v1; rsum1 += v2 + v3;
            }
            if (BROW) { v0 += br0; v1 += br0; v2 += br1; v3 += br1; }
            if (RDIV) { v0 *= br0; v1 *= br0; v2 *= br1; v3 *= br1; }
            if (RES) {
                float2 ra = *(const float2*)(resg + (size_t)b*sC + (size_t)r0*ldc + cc);
                float2 rb = *(const float2*)(resg + (size_t)b*sC + (size_t)(r0+8)*ldc + cc);
                v0 += ra.x; v1 += ra.y; v2 += rb.x; v3 += rb.y;
            }
            if (OUTF) {
                float* Cb = (float*)Cg + (size_t)b * sC;
                float2 o0 = {v0, v1}, o1 = {v2, v3};
                *(float2*)(Cb + (size_t)r0*ldc + cc) = o0;
                *(float2*)(Cb + (size_t)(r0+8)*ldc + cc) = o1;
            } else {
                __half* Cb = (__half*)Cg + (size_t)b * sC;
                *(__half2*)(Cb + (size_t)r0*ldc + cc) = __floats2half2_rn(v0, v1);
                *(__half2*)(Cb + (size_t)(r0+8)*ldc + cc) = __floats2half2_rn(v2, v3);
            }
        }
        if (EXPSUM) {
            #pragma unroll
            for (int o = 1; o < 4; o <<= 1) {
                rsum0 += __shfl_xor_sync(0xffffffffu, rsum0, o);
                rsum1 += __shfl_xor_sync(0xffffffffu, rsum1, o);
            }
            if ((lane & 3) == 0) {
                atomicAdd(rsb + r0, rsum0);
                atomicAdd(rsb + r0 + 8, rsum1);
            }
        }
    }
}

// ============================ launch ============================
extern "C" void kernel_launch(void* const* d_in, const int* in_sizes, int n_in,
                              void* d_out, int out_size) {
    const float* inp   = (const float*)d_in[0];
    const float* gamma = (const float*)d_in[1];
    const float* beta  = (const float*)d_in[2];
    const float* Wq    = (const float*)d_in[3];
    const float* bq    = (const float*)d_in[4];
    const float* Wk    = (const float*)d_in[5];
    const float* bk    = (const float*)d_in[6];
    const float* Wv    = (const float*)d_in[7];
    const float* bv    = (const float*)d_in[8];
    const float* Wo    = (const float*)d_in[9];
    const float* bo    = (const float*)d_in[10];
    float* out = (float*)d_out;

    void *pxt, *pqkv, *ps, *pa, *hwqkv, *hwo, *pbqkv, *prs;
    cudaGetSymbolAddress(&pxt, g_xt);
    cudaGetSymbolAddress(&pqkv, g_qkv);
    cudaGetSymbolAddress(&ps, g_s);
    cudaGetSymbolAddress(&pa, g_a);
    cudaGetSymbolAddress(&hwqkv, g_hwqkv);
    cudaGetSymbolAddress(&hwo, g_hwo);
    cudaGetSymbolAddress(&pbqkv, g_bqkv);
    cudaGetSymbolAddress(&prs, g_rsum);

    const long sNC  = (long)HW * C;
    const long sN3C = (long)HW * 3 * C;
    const long sHH  = (long)HW * HW;

    cudaFuncSetAttribute(gemm_tn<true,false,false,false,false,false>, cudaFuncAttributeMaxDynamicSharedMemorySize, SMEM_TOT);
    cudaFuncSetAttribute(gemm_tn<false,false,false,false,true,false>, cudaFuncAttributeMaxDynamicSharedMemorySize, SMEM_TOT);
    cudaFuncSetAttribute(gemm_tn<false,false,false,true,false,true>, cudaFuncAttributeMaxDynamicSharedMemorySize, SMEM_TOT);
    cudaFuncSetAttribute(gemm_tn<true,true,true,false,false,false>, cudaFuncAttributeMaxDynamicSharedMemorySize, SMEM_TOT);

    // GroupNorm (512) + weight convert (1024) + rsum zero (16)
    prep_kernel<<<1552, 256>>>(inp, gamma, beta, Wq, Wk, Wv, Wo, bq, bk, bv);

    // QKV_t[n][o] = sum_c x_t[n][c] Wqkv[o][c] + bqkv[o]  (M=1024, N=1536)
    gemm_tn<true,false,false,false,false,false><<<dim3(3*C/128, HW/128, BATCH), NTHR, SMEM_TOT>>>(
        (const __half*)pxt, (const __half*)hwqkv, pqkv, (const float*)pbqkv, nullptr, nullptr,
        3*C, C, C, C, 3*C, sNC, 0, sN3C);

    // P_unnorm[n][m] = exp(scale * sum_c Q K) ; rsum[n] += row sums
    gemm_tn<false,false,false,false,true,false><<<dim3(HW/128, HW/128, BATCH), NTHR, SMEM_TOT>>>(
        (const __half*)pqkv, (const __half*)pqkv + C, ps, nullptr, nullptr, (float*)prs,
        HW, C, 3*C, 3*C, HW, sN3C, sN3C, sHH);

    // A_t[n][c] = (sum_m P_unnorm[n][m] V_t[m][c]) / rsum[n]
    gemm_tn<false,false,false,true,false,true><<<dim3(C/128, HW/128, BATCH), NTHR, SMEM_TOT>>>(
        (const __half*)ps, (const __half*)pqkv + 2*C, pa, nullptr, nullptr, (float*)prs,
        C, HW, HW, 3*C, C, sHH, sN3C, sNC);

    // out[o][n] = sum_c Wo[o][c] A_t[n][c] + bo[o] + inp[o][n]   (fp32 out)
    gemm_tn<true,true,true,false,false,false><<<dim3(HW/128, C/128, BATCH), NTHR, SMEM_TOT>>>(
        (const __half*)hwo, (const __half*)pa, out, bo, inp, nullptr,
        HW, C, C, C, HW, 0, sNC, sNC);
}

// round 16
// speedup vs baseline: 1.1735x; 1.0183x over previous
#include <cuda_runtime.h>
#include <cuda_fp16.h>
#include <math.h>
#include <stdint.h>

#define BATCH 16
#define C 512
#define HW 1024
#define NGROUP 32
#define CPG 16
#define GSIZE (CPG*HW)
#define QK_SCALE 0.04419417382415922f  // 1/sqrt(512)

// -------- scratch (static device globals; no runtime allocation) --------
__device__ __half g_xt[BATCH*HW*C];     // normalized input, transposed [b][n][c]
__device__ __half g_qkv[BATCH*HW*3*C];  // [b][n][0..C)=Q, [C..2C)=K, [2C..3C)=V_t
__device__ __half g_s[BATCH*HW*HW];     // unnormalized probs exp(S*scale)
__device__ __half g_a[BATCH*HW*C];      // A_t [b][n][c]
__device__ __half g_hwqkv[3*C*C];       // Wq | Wk | Wv  (row-major [o][c])
__device__ __half g_hwo[C*C];
__device__ float  g_bqkv[3*C];          // bq | bk | bv
__device__ float  g_rsum[BATCH*HW];     // softmax row sums (atomic accumulated)

// ============================ fused prep ============================
__global__ __launch_bounds__(256) void prep_kernel(
    const float* __restrict__ inp,
    const float* __restrict__ gamma, const float* __restrict__ beta,
    const float* __restrict__ Wq, const float* __restrict__ Wk,
    const float* __restrict__ Wv, const float* __restrict__ Wo,
    const float* __restrict__ bq, const float* __restrict__ bk,
    const float* __restrict__ bv)
{
    if (blockIdx.x >= 1536) {
        int i = (blockIdx.x - 1536)*1024 + threadIdx.x*4;
        float4 z = {0.f, 0.f, 0.f, 0.f};
        *(float4*)(g_rsum + i) = z;
        return;
    }
    if (blockIdx.x >= 512) {
        int i = blockIdx.x - 512;
        int which = i >> 8;
        int blk = i & 255;
        const float* s = which == 0 ? Wq : which == 1 ? Wk : which == 2 ? Wv : Wo;
        __half* d = which == 3 ? g_hwo : (g_hwqkv + (size_t)which * C * C);
        int e = (blk*256 + threadIdx.x)*4;
        float4 v = *(const float4*)(s + e);
        *(__half2*)(d + e)     = __floats2half2_rn(v.x, v.y);
        *(__half2*)(d + e + 2) = __floats2half2_rn(v.z, v.w);
        if (i == 0) {
            int t = threadIdx.x;
            #pragma unroll
            for (int p = 0; p < 2; p++) {
                int j = t + p*256;
                g_bqkv[j] = bq[j];
                g_bqkv[C + j] = bk[j];
                g_bqkv[2*C + j] = bv[j];
            }
        }
        return;
    }

    int bg = blockIdx.x;
    int b = bg / NGROUP, g = bg % NGROUP;
    const float* src = inp + (size_t)bg * GSIZE;

    float vreg[4][CPG];
    float s = 0.f, ss = 0.f;
    #pragma unroll
    for (int p = 0; p < 4; p++) {
        int n = threadIdx.x + p*256;
        #pragma unroll
        for (int c = 0; c < CPG; c++) {
            float x = src[c*HW + n];
            vreg[p][c] = x;
            s += x; ss += x*x;
        }
    }
    __shared__ float sh1[8], sh2[8];
    #pragma unroll
    for (int o = 16; o > 0; o >>= 1) {
        s  += __shfl_down_sync(0xffffffffu, s,  o);
        ss += __shfl_down_sync(0xffffffffu, ss, o);
    }
    int lane = threadIdx.x & 31, wid = threadIdx.x >> 5;
    if (lane == 0) { sh1[wid] = s; sh2[wid] = ss; }
    __syncthreads();
    if (threadIdx.x == 0) {
        float t1 = 0.f, t2 = 0.f;
        #pragma unroll
        for (int i = 0; i < 8; i++) { t1 += sh1[i]; t2 += sh2[i]; }
        sh1[0] = t1; sh2[0] = t2;
    }
    __syncthreads();
    float mu   = sh1[0] * (1.f/GSIZE);
    float var  = sh2[0] * (1.f/GSIZE) - mu*mu;
    float rstd = rsqrtf(var + 1e-6f);

    float ga[CPG], be[CPG];
    #pragma unroll
    for (int c = 0; c < CPG; c++) {
        ga[c] = gamma[g*CPG + c] * rstd;
        be[c] = beta[g*CPG + c];
    }

    __half* dst = g_xt + (size_t)b*HW*C + g*CPG;
    #pragma unroll
    for (int p = 0; p < 4; p++) {
        int n = threadIdx.x + p*256;
        __half2 hh[8];
        #pragma unroll
        for (int c = 0; c < 8; c++) {
            float o0 = (vreg[p][2*c  ] - mu) * ga[2*c  ] + be[2*c  ];
            float o1 = (vreg[p][2*c+1] - mu) * ga[2*c+1] + be[2*c+1];
            hh[c] = __floats2half2_rn(o0, o1);
        }
        __half* d = dst + (size_t)n * C;
        *(uint4*)(d)     = *(uint4*)(hh);
        *(uint4*)(d + 8) = *(uint4*)(hh + 4);
    }
}

// ============================ unified TN fp16 GEMM (128x128x64, 4 warps) ============================
// C[b][m][n] = sum_k A[m][k]*B[n][k].  A always [m][k] k-contig.
// BTRANS: B stored [k][n] n-contig (ldmatrix.trans).
// EXPSUM: epilogue writes exp(acc*QK_SCALE), atomically accumulates row sums.
// RDIV:   epilogue scales rows by 1/rsum (loads hoisted, MLP=8).
// Staging cp.async interleaved across the 4 ks blocks (issue smoothing).

#define STAGE_BYTES 32768
#define NSTAGE 3
#define SMEM_TOT (NSTAGE*STAGE_BYTES)
#define NTHR 128
#define BK 64

__device__ __forceinline__ void cp16(uint32_t saddr, const void* g) {
    asm volatile("cp.async.cg.shared.global [%0], [%1], 16;" :: "r"(saddr), "l"(g));
}
#define LDSM4(R0,R1,R2,R3,ADDR) \
    asm volatile("ldmatrix.sync.aligned.m8n8.x4.shared.b16 {%0,%1,%2,%3}, [%4];" \
        : "=r"(R0), "=r"(R1), "=r"(R2), "=r"(R3) : "r"(ADDR))
#define LDSM4T(R0,R1,R2,R3,ADDR) \
    asm volatile("ldmatrix.sync.aligned.m8n8.x4.trans.shared.b16 {%0,%1,%2,%3}, [%4];" \
        : "=r"(R0), "=r"(R1), "=r"(R2), "=r"(R3) : "r"(ADDR))

template<bool BROW, bool RES, bool OUTF, bool BTRANS, bool EXPSUM, bool RDIV>
__global__ __launch_bounds__(NTHR, 2) void gemm_tn(
    const __half* __restrict__ Ag, const __half* __restrict__ Bg,
    void* __restrict__ Cg, const float* __restrict__ bias,
    const float* __restrict__ resg, float* __restrict__ rs,
    int N, int K, int lda, int ldb, int ldc,
    long sA, long sB, long sC)
{
    extern __shared__ float smem[];
    const uint32_t smem_u32 = (uint32_t)__cvta_generic_to_shared(smem);

    const int t = threadIdx.x, lane = t & 31, w = t >> 5;
    const int m0 = blockIdx.y * 128, n0 = blockIdx.x * 128, b = blockIdx.z;
    const __half* Ab = Ag + (size_t)b * sA + (size_t)m0 * lda;
    const __half* Bb;
    if (BTRANS) Bb = Bg + (size_t)b * sB + n0;
    else        Bb = Bg + (size_t)b * sB + (size_t)n0 * ldb;

    uint32_t sAoff[8], gAo[8], sBoff[8], gBo[8];
    #pragma unroll
    for (int p = 0; p < 8; p++) {
        int idx = t + NTHR*p;
        int rowA = idx >> 3, gcA = idx & 7;
        sAoff[p] = (uint32_t)((rowA*8 + (gcA ^ (rowA & 7))) * 16);
        gAo[p] = (uint32_t)(rowA * lda + gcA*8);
        if (BTRANS) {
            int row = idx >> 4, gc = idx & 15;
            sBoff[p] = (uint32_t)((row*16 + (gc ^ (row & 7))) * 16);
            gBo[p] = (uint32_t)(row * ldb + gc*8);
        } else {
            sBoff[p] = sAoff[p];
            gBo[p] = (uint32_t)(rowA * ldb + gcA*8);
        }
    }

    const int wm = (w & 1) * 64, wn = (w >> 1) * 64;
    int amrow[4], am7[4];
    #pragma unroll
    for (int mi = 0; mi < 4; mi++) {
        int m = wm + mi*16 + (lane & 7) + ((lane & 8) ? 8 : 0);
        amrow[mi] = m * 8; am7[mi] = m & 7;
    }
    const int kgA = (lane & 16) ? 1 : 0;

    int bnrow[4], bn7[4];
    uint32_t btoff[4];
    const int kgB = (lane & 8) ? 1 : 0;
    #pragma unroll
    for (int P = 0; P < 4; P++) {
        if (BTRANS) {
            int rk = (lane & 7) + ((lane & 8) ? 8 : 0);
            int ngU = ((wn + P*16) >> 3) + ((lane & 16) ? 1 : 0);
            btoff[P] = (uint32_t)((rk*16 + (ngU ^ (rk & 7))) * 16);
        } else {
            int n = wn + P*16 + (lane & 7) + ((lane & 16) ? 8 : 0);
            bnrow[P] = n * 8; bn7[P] = n & 7;
        }
    }

    float acc[4][8][4];
    #pragma unroll
    for (int i = 0; i < 4; i++)
        #pragma unroll
        for (int j = 0; j < 8; j++)
            #pragma unroll
            for (int r = 0; r < 4; r++) acc[i][j][r] = 0.f;

    const int NTILES = K >> 6;

    #pragma unroll
    for (int kt = 0; kt < 2; kt++) {
        uint32_t sa = smem_u32 + kt*STAGE_BYTES, sb = sa + 16384;
        #pragma unroll
        for (int p = 0; p < 8; p++) cp16(sa + sAoff[p], Ab + gAo[p] + kt*BK);
        #pragma unroll
        for (int p = 0; p < 8; p++)
            cp16(sb + sBoff[p], Bb + gBo[p] + (BTRANS ? kt*BK*ldb : kt*BK));
        asm volatile("cp.async.commit_group;" ::: "memory");
    }

    int buf = 0, sbuf = 2;
    for (int kt = 0; kt < NTILES; kt++) {
        if (kt + 1 < NTILES) asm volatile("cp.async.wait_group 1;" ::: "memory");
        else                 asm volatile("cp.async.wait_group 0;" ::: "memory");
        __syncthreads();

        const bool do_stage = (kt + 2 < NTILES);
        const int k0 = (kt + 2) << 6;
        const uint32_t nsa = smem_u32 + sbuf*STAGE_BYTES;
        const uint32_t nsb = nsa + 16384;

        const uint32_t sa = smem_u32 + buf*STAGE_BYTES;
        const uint32_t sb = sa + 16384;

        #pragma unroll
        for (int ks = 0; ks < 4; ks++) {
            // interleaved staging: 4 cp.async per ks block (A at ks0/1, B at ks2/3)
            if (do_stage) {
                if (ks < 2) {
                    #pragma unroll
                    for (int p = 0; p < 4; p++) {
                        int q = ks*4 + p;
                        cp16(nsa + sAoff[q], Ab + gAo[q] + k0);
                    }
                } else {
                    #pragma unroll
                    for (int p = 0; p < 4; p++) {
                        int q = (ks-2)*4 + p;
                        cp16(nsb + sBoff[q], Bb + gBo[q] + (BTRANS ? k0*ldb : k0));
                    }
                }
            }

            unsigned a[4][4];
            #pragma unroll
            for (int mi = 0; mi < 4; mi++) {
                uint32_t ad = sa + (uint32_t)((amrow[mi] + ((2*ks + kgA) ^ am7[mi])) * 16);
                LDSM4(a[mi][0], a[mi][1], a[mi][2], a[mi][3], ad);
            }
            unsigned bf[8][2];
            #pragma unroll
            for (int P = 0; P < 4; P++) {
                if (BTRANS) {
                    uint32_t bd = sb + btoff[P] + (uint32_t)(ks * 4096);
                    LDSM4T(bf[2*P][0], bf[2*P][1], bf[2*P+1][0], bf[2*P+1][1], bd);
                } else {
                    uint32_t bd = sb + (uint32_t)((bnrow[P] + ((2*ks + kgB) ^ bn7[P])) * 16);
                    LDSM4(bf[2*P][0], bf[2*P][1], bf[2*P+1][0], bf[2*P+1][1], bd);
                }
            }
            #pragma unroll
            for (int mi = 0; mi < 4; mi++)
                #pragma unroll
                for (int ni = 0; ni < 8; ni++)
                    asm volatile(
                        "mma.sync.aligned.m16n8k16.row.col.f32.f16.f16.f32 "
                        "{%0,%1,%2,%3}, {%4,%5,%6,%7}, {%8,%9}, {%0,%1,%2,%3};"
                        : "+f"(acc[mi][ni][0]), "+f"(acc[mi][ni][1]),
                          "+f"(acc[mi][ni][2]), "+f"(acc[mi][ni][3])
                        : "r"(a[mi][0]), "r"(a[mi][1]), "r"(a[mi][2]), "r"(a[mi][3]),
                          "r"(bf[ni][0]), "r"(bf[ni][1]));
        }
        if (do_stage) asm volatile("cp.async.commit_group;" ::: "memory");

        buf = (buf == 2) ? 0 : buf + 1;
        sbuf = (sbuf == 2) ? 0 : sbuf + 1;
    }

    // ---- epilogue (hoisted row-scalar loads) ----
    float* rsb = (EXPSUM || RDIV) ? (rs + (size_t)b * HW) : nullptr;
    float rowA8[8];
    #pragma unroll
    for (int mi = 0; mi < 4; mi++) {
        int r0 = m0 + wm + mi*16 + (lane >> 2);
        if (BROW) { rowA8[2*mi] = bias[r0]; rowA8[2*mi+1] = bias[r0 + 8]; }
        else if (RDIV) { rowA8[2*mi] = rsb[r0]; rowA8[2*mi+1] = rsb[r0 + 8]; }
        else { rowA8[2*mi] = 0.f; rowA8[2*mi+1] = 0.f; }
    }
    if (RDIV) {
        #pragma unroll
        for (int i = 0; i < 8; i++) rowA8[i] = 1.f / rowA8[i];
    }

    #pragma unroll
    for (int mi = 0; mi < 4; mi++) {
        int r0 = m0 + wm + mi*16 + (lane >> 2);
        float br0 = rowA8[2*mi], br1 = rowA8[2*mi+1];
        float rsum0 = 0.f, rsum1 = 0.f;
        #pragma unroll
        for (int ni = 0; ni < 8; ni++) {
            int cc = n0 + wn + ni*8 + (lane & 3)*2;
            float v0 = acc[mi][ni][0], v1 = acc[mi][ni][1];
            float v2 = acc[mi][ni][2], v3 = acc[mi][ni][3];
            if (EXPSUM) {
                v0 = __expf(v0 * QK_SCALE); v1 = __expf(v1 * QK_SCALE);
                v2 = __expf(v2 * QK_SCALE); v3 = __expf(v3 * QK_SCALE);
                rsum0 += v0 + v1; rsum1 += v2 + v3;
            }
            if (BROW) { v0 += br0; v1 += br0; v2 += br1; v3 += br1; }
            if (RDIV) { v0 *= br0; v1 *= br0; v2 *= br1; v3 *= br1; }
            if (RES) {
                float2 ra = *(const float2*)(resg + (size_t)b*sC + (size_t)r0*ldc + cc);
                float2 rb = *(const float2*)(resg + (size_t)b*sC + (size_t)(r0+8)*ldc + cc);
                v0 += ra.x; v1 += ra.y; v2 += rb.x; v3 += rb.y;
            }
            if (OUTF) {
                float* Cb = (float*)Cg + (size_t)b * sC;
                float2 o0 = {v0, v1}, o1 = {v2, v3};
                *(float2*)(Cb + (size_t)r0*ldc + cc) = o0;
                *(float2*)(Cb + (size_t)(r0+8)*ldc + cc) = o1;
            } else {
                __half* Cb = (__half*)Cg + (size_t)b * sC;
                *(__half2*)(Cb + (size_t)r0*ldc + cc) = __floats2half2_rn(v0, v1);
                *(__half2*)(Cb + (size_t)(r0+8)*ldc + cc) = __floats2half2_rn(v2, v3);
            }
        }
        if (EXPSUM) {
            #pragma unroll
            for (int o = 1; o < 4; o <<= 1) {
                rsum0 += __shfl_xor_sync(0xffffffffu, rsum0, o);
                rsum1 += __shfl_xor_sync(0xffffffffu, rsum1, o);
            }
            if ((lane & 3) == 0) {
                atomicAdd(rsb + r0, rsum0);
                atomicAdd(rsb + r0 + 8, rsum1);
            }
        }
    }
}

// ============================ launch ============================
extern "C" void kernel_launch(void* const* d_in, const int* in_sizes, int n_in,
                              void* d_out, int out_size) {
    const float* inp   = (const float*)d_in[0];
    const float* gamma = (const float*)d_in[1];
    const float* beta  = (const float*)d_in[2];
    const float* Wq    = (const float*)d_in[3];
    const float* bq    = (const float*)d_in[4];
    const float* Wk    = (const float*)d_in[5];
    const float* bk    = (const float*)d_in[6];
    const float* Wv    = (const float*)d_in[7];
    const float* bv    = (const float*)d_in[8];
    const float* Wo    = (const float*)d_in[9];
    const float* bo    = (const float*)d_in[10];
    float* out = (float*)d_out;

    void *pxt, *pqkv, *ps, *pa, *hwqkv, *hwo, *pbqkv, *prs;
    cudaGetSymbolAddress(&pxt, g_xt);
    cudaGetSymbolAddress(&pqkv, g_qkv);
    cudaGetSymbolAddress(&ps, g_s);
    cudaGetSymbolAddress(&pa, g_a);
    cudaGetSymbolAddress(&hwqkv, g_hwqkv);
    cudaGetSymbolAddress(&hwo, g_hwo);
    cudaGetSymbolAddress(&pbqkv, g_bqkv);
    cudaGetSymbolAddress(&prs, g_rsum);

    const long sNC  = (long)HW * C;
    const long sN3C = (long)HW * 3 * C;
    const long sHH  = (long)HW * HW;

    cudaFuncSetAttribute(gemm_tn<true,false,false,false,false,false>, cudaFuncAttributeMaxDynamicSharedMemorySize, SMEM_TOT);
    cudaFuncSetAttribute(gemm_tn<false,false,false,false,true,false>, cudaFuncAttributeMaxDynamicSharedMemorySize, SMEM_TOT);
    cudaFuncSetAttribute(gemm_tn<false,false,false,true,false,true>, cudaFuncAttributeMaxDynamicSharedMemorySize, SMEM_TOT);
    cudaFuncSetAttribute(gemm_tn<true,true,true,false,false,false>, cudaFuncAttributeMaxDynamicSharedMemorySize, SMEM_TOT);

    // GroupNorm (512) + weight convert (1024) + rsum zero (16)
    prep_kernel<<<1552, 256>>>(inp, gamma, beta, Wq, Wk, Wv, Wo, bq, bk, bv);

    // QKV_t[n][o] = sum_c x_t[n][c] Wqkv[o][c] + bqkv[o]  (M=1024, N=1536)
    gemm_tn<true,false,false,false,false,false><<<dim3(3*C/128, HW/128, BATCH), NTHR, SMEM_TOT>>>(
        (const __half*)pxt, (const __half*)hwqkv, pqkv, (const float*)pbqkv, nullptr, nullptr,
        3*C, C, C, C, 3*C, sNC, 0, sN3C);

    // P_unnorm[n][m] = exp(scale * sum_c Q K) ; rsum[n] += row sums
    gemm_tn<false,false,false,false,true,false><<<dim3(HW/128, HW/128, BATCH), NTHR, SMEM_TOT>>>(
        (const __half*)pqkv, (const __half*)pqkv + C, ps, nullptr, nullptr, (float*)prs,
        HW, C, 3*C, 3*C, HW, sN3C, sN3C, sHH);

    // A_t[n][c] = (sum_m P_unnorm[n][m] V_t[m][c]) / rsum[n]
    gemm_tn<false,false,false,true,false,true><<<dim3(C/128, HW/128, BATCH), NTHR, SMEM_TOT>>>(
        (const __half*)ps, (const __half*)pqkv + 2*C, pa, nullptr, nullptr, (float*)prs,
        C, HW, HW, 3*C, C, sHH, sN3C, sNC);

    // out[o][n] = sum_c Wo[o][c] A_t[n][c] + bo[o] + inp[o][n]   (fp32 out)
    gemm_tn<true,true,true,false,false,false><<<dim3(HW/128, C/128, BATCH), NTHR, SMEM_TOT>>>(
        (const __half*)hwo, (const __half*)pa, out, bo, inp, nullptr,
        HW, C, C, C, HW, 0, sNC, sNC);
}